// round 11
// baseline (speedup 1.0000x reference)
#include <cuda_runtime.h>
#include <cuda_bf16.h>
#include <cstdint>

#define SEQ    4096
#define DMODEL 1024
#define DINNER 2048
#define DSTATE 64
#define NH     16
#define NBATCH 2
#define BL     (NBATCH * SEQ)      /* 8192 rows */
#define DXZ    (2 * DINNER)        /* 4096 */
#define NPROJ  (NH + 2 * DSTATE)   /* 144 */
#define NPROJP 160                 /* padded */

// ---------------- scratch (device globals: no allocation allowed) ----------------
__device__ float g_xz [BL * DXZ];              // in_proj output (x | z)
__device__ float g_u  [BL * DINNER];           // conv+silu (b,l,d)
__device__ float g_uT [NBATCH * DINNER * SEQ]; // (b,d,l)
__device__ float g_dtT[NBATCH * NH * SEQ];     // softplus(dt), (b,h,l)
__device__ float g_Bm [BL * DSTATE];           // (b,l,n)
__device__ float g_Cm [BL * DSTATE];
__device__ float g_y1 [BL * DINNER];           // scan out + u*D
__device__ float g_wT [DINNER * NPROJP];       // dt_proj_w transposed, padded

// bf16 split operands for tensor-core GEMMs (16B aligned for cp.async)
__device__ __align__(16) __nv_bfloat16 g_Ahi[BL * DMODEL],      g_Alo[BL * DMODEL];
__device__ __align__(16) __nv_bfloat16 g_Wihi[DXZ * DMODEL],    g_Wilo[DXZ * DMODEL];
__device__ __align__(16) __nv_bfloat16 g_Wohi[DMODEL * DINNER], g_Wolo[DMODEL * DINNER];
__device__ __align__(16) __nv_bfloat16 g_Chi[BL * DINNER],      g_Clo[BL * DINNER];

__device__ __forceinline__ float ex2f(float x) {
    float r;
    asm("ex2.approx.ftz.f32 %0, %1;" : "=f"(r) : "f"(x));
    return r;
}
__device__ __forceinline__ uint32_t smem_u32(const void* p) {
    uint32_t a;
    asm("{ .reg .u64 t; cvta.to.shared.u64 t, %1; cvt.u32.u64 %0, t; }" : "=r"(a) : "l"(p));
    return a;
}

// ============ split fp32 -> bf16 hi/lo ============
__global__ __launch_bounds__(256) void split_kernel(const float* __restrict__ x,
                                                    __nv_bfloat16* __restrict__ hi,
                                                    __nv_bfloat16* __restrict__ lo) {
    int i = (blockIdx.x * 256 + threadIdx.x) * 4;
    float4 v = *(const float4*)(x + i);
    float f[4] = {v.x, v.y, v.z, v.w};
#pragma unroll
    for (int j = 0; j < 4; ++j) {
        __nv_bfloat16 h = __float2bfloat16(f[j]);
        hi[i + j] = h;
        lo[i + j] = __float2bfloat16(f[j] - __bfloat162float(h));
    }
}

// ============ mma.sync bf16 GEMM: C[M,N] = split-3( A @ B^T ) ============
// 128x128 tile, BK=64, 512 threads (16 warps, 32x32 per warp), 3-stage cp.async
// pipeline, XOR-swizzled smem. smem: As[3] @0 (48KB), Bs[3] @49152 (48KB).
#define STG_BYTES 16384
#define GEMM_SMEM 98304

__device__ __forceinline__ void stage_load(const __nv_bfloat16* __restrict__ A,
                                           const __nv_bfloat16* __restrict__ B,
                                           int K, int bm, int bn, int k0,
                                           char* smA, char* smB, int tid) {
#pragma unroll
    for (int i = 0; i < 2; ++i) {
        int q = tid + i * 512;          // 0..1023 chunk id
        int row = q >> 3, c = q & 7;    // 128 rows x 8 chunks(16B) per row
        int pc = c ^ (row & 7);         // swizzle
        uint32_t da = smem_u32(smA + (row * 8 + pc) * 16);
        const void* ga = (const void*)(A + (size_t)(bm + row) * K + k0 + c * 8);
        asm volatile("cp.async.cg.shared.global [%0], [%1], 16;" :: "r"(da), "l"(ga));
        uint32_t db = smem_u32(smB + (row * 8 + pc) * 16);
        const void* gb = (const void*)(B + (size_t)(bn + row) * K + k0 + c * 8);
        asm volatile("cp.async.cg.shared.global [%0], [%1], 16;" :: "r"(db), "l"(gb));
    }
}

__device__ __forceinline__ void chunk_src(int cc, int ksec,
                                          const __nv_bfloat16* Ahi, const __nv_bfloat16* Alo,
                                          const __nv_bfloat16* Bhi, const __nv_bfloat16* Blo,
                                          const __nv_bfloat16** As, const __nv_bfloat16** Bs,
                                          int* k0) {
    int s = cc / ksec;
    *k0 = (cc - s * ksec) << 6;
    *As = (s < 2) ? Ahi : Alo;
    *Bs = (s == 1) ? Blo : Bhi;
}

__global__ __launch_bounds__(512) void mma_gemm(const __nv_bfloat16* __restrict__ Ahi,
                                                const __nv_bfloat16* __restrict__ Alo,
                                                const __nv_bfloat16* __restrict__ Bhi,
                                                const __nv_bfloat16* __restrict__ Blo,
                                                float* __restrict__ C, int N, int K) {
    extern __shared__ char smem[];
    const int tid = threadIdx.x;
    const int wid = tid >> 5, lane = tid & 31;
    const int wm = (wid >> 2) * 32;     // warp m offset in tile (16 warps: 4x4)
    const int wn = (wid & 3) * 32;      // warp n offset in tile
    const int bm = blockIdx.y * 128;
    const int bn = blockIdx.x * 128;

    float acc[2][4][4];
#pragma unroll
    for (int a = 0; a < 2; ++a)
#pragma unroll
        for (int b = 0; b < 4; ++b)
#pragma unroll
            for (int c = 0; c < 4; ++c) acc[a][b][c] = 0.f;

    const int ksec = K >> 6;
    const int nch = 3 * ksec;
    const __nv_bfloat16 *pA, *pB;
    int pk;

    // prologue: preload chunks 0 and 1 into stages 0 and 1
    chunk_src(0, ksec, Ahi, Alo, Bhi, Blo, &pA, &pB, &pk);
    stage_load(pA, pB, K, bm, bn, pk, smem, smem + 3 * STG_BYTES, tid);
    asm volatile("cp.async.commit_group;" ::: "memory");
    if (1 < nch) {
        chunk_src(1, ksec, Ahi, Alo, Bhi, Blo, &pA, &pB, &pk);
        stage_load(pA, pB, K, bm, bn, pk,
                   smem + STG_BYTES, smem + 3 * STG_BYTES + STG_BYTES, tid);
        asm volatile("cp.async.commit_group;" ::: "memory");
    }

    for (int cc = 0; cc < nch; ++cc) {
        const int st = cc % 3;
        if (cc + 2 < nch) {
            const int st2 = (cc + 2) % 3;
            chunk_src(cc + 2, ksec, Ahi, Alo, Bhi, Blo, &pA, &pB, &pk);
            stage_load(pA, pB, K, bm, bn, pk,
                       smem + st2 * STG_BYTES, smem + 3 * STG_BYTES + st2 * STG_BYTES, tid);
            asm volatile("cp.async.commit_group;" ::: "memory");
            asm volatile("cp.async.wait_group 2;" ::: "memory");
        } else if (cc + 1 < nch) {
            asm volatile("cp.async.wait_group 1;" ::: "memory");
        } else {
            asm volatile("cp.async.wait_group 0;" ::: "memory");
        }
        __syncthreads();

        const char* sA = smem + st * STG_BYTES;
        const char* sB = smem + 3 * STG_BYTES + st * STG_BYTES;
#pragma unroll
        for (int kk = 0; kk < 4; ++kk) {        // 4 x k16 within BK=64
            uint32_t a[2][4];
#pragma unroll
            for (int mt = 0; mt < 2; ++mt) {
                int row = wm + mt * 16 + (lane & 15);
                int c = kk * 2 + (lane >> 4);
                uint32_t ad = smem_u32(sA + (row * 8 + (c ^ (row & 7))) * 16);
                asm volatile("ldmatrix.sync.aligned.m8n8.x4.shared.b16 {%0,%1,%2,%3}, [%4];"
                             : "=r"(a[mt][0]), "=r"(a[mt][1]), "=r"(a[mt][2]), "=r"(a[mt][3])
                             : "r"(ad));
            }
            uint32_t b[4][2];
#pragma unroll
            for (int pt = 0; pt < 2; ++pt) {
                int row = wn + pt * 16 + (lane & 15);
                int c = kk * 2 + (lane >> 4);
                uint32_t bd = smem_u32(sB + (row * 8 + (c ^ (row & 7))) * 16);
                uint32_t r0, r1, r2, r3;
                asm volatile("ldmatrix.sync.aligned.m8n8.x4.shared.b16 {%0,%1,%2,%3}, [%4];"
                             : "=r"(r0), "=r"(r1), "=r"(r2), "=r"(r3) : "r"(bd));
                b[2 * pt][0] = r0; b[2 * pt + 1][0] = r1;
                b[2 * pt][1] = r2; b[2 * pt + 1][1] = r3;
            }
#pragma unroll
            for (int mt = 0; mt < 2; ++mt)
#pragma unroll
                for (int nt = 0; nt < 4; ++nt) {
                    asm volatile(
                        "mma.sync.aligned.m16n8k16.row.col.f32.bf16.bf16.f32 "
                        "{%0,%1,%2,%3}, {%4,%5,%6,%7}, {%8,%9}, {%0,%1,%2,%3};"
                        : "+f"(acc[mt][nt][0]), "+f"(acc[mt][nt][1]),
                          "+f"(acc[mt][nt][2]), "+f"(acc[mt][nt][3])
                        : "r"(a[mt][0]), "r"(a[mt][1]), "r"(a[mt][2]), "r"(a[mt][3]),
                          "r"(b[nt][0]), "r"(b[nt][1]));
                }
        }
        __syncthreads();
    }

    // epilogue
    const int g = lane >> 2, t = lane & 3;
#pragma unroll
    for (int mt = 0; mt < 2; ++mt) {
        int row0 = bm + wm + mt * 16 + g;
#pragma unroll
        for (int nt = 0; nt < 4; ++nt) {
            int col = bn + wn + nt * 8 + 2 * t;
            *(float2*)(C + (size_t)row0 * N + col) = make_float2(acc[mt][nt][0], acc[mt][nt][1]);
            *(float2*)(C + (size_t)(row0 + 8) * N + col) = make_float2(acc[mt][nt][2], acc[mt][nt][3]);
        }
    }
}

// ---------------- transpose dt_proj_w -> wT[k][c] (padded to 160) ----------------
__global__ void wT_kernel(const float* __restrict__ w) {
    int idx = blockIdx.x * 256 + threadIdx.x;
    if (idx >= DINNER * NPROJP) return;
    int k = idx / NPROJP, c = idx % NPROJP;
    g_wT[idx] = (c < NPROJ) ? w[(size_t)c * DINNER + k] : 0.f;
}

// ---------------- depthwise causal conv (w=4) + silu, writes u and uT ----------------
__global__ __launch_bounds__(1024) void conv_silu_kernel(const float* __restrict__ cw,
                                                         const float* __restrict__ cb) {
    __shared__ float sm[32][33];
    const int tx = threadIdx.x, ty = threadIdx.y;
    const int b = blockIdx.z;
    const int d = blockIdx.x * 32 + tx;
    const int l = blockIdx.y * 32 + ty;
    const float* xcol = g_xz + (size_t)b * SEQ * DXZ + d;  // x = cols [0,2048)
    float acc = cb[d];
#pragma unroll
    for (int k = 0; k < 4; ++k) {
        int ll = l - 3 + k;
        if (ll >= 0) acc = fmaf(xcol[(size_t)ll * DXZ], cw[d * 4 + k], acc);
    }
    float u = acc / (1.f + __expf(-acc));  // silu
    g_u[((size_t)b * SEQ + l) * DINNER + d] = u;
    sm[ty][tx] = u;
    __syncthreads();
    const int dd = blockIdx.x * 32 + ty;
    const int ll2 = blockIdx.y * 32 + tx;
    g_uT[((size_t)b * DINNER + dd) * SEQ + ll2] = sm[tx][ty];
}

// ---------------- x_proj: warp per 4 rows; lane owns cols lane+32j ----------------
__global__ __launch_bounds__(256) void xproj_kernel(const float* __restrict__ bias,
                                                    const float* __restrict__ dt_bias) {
    const int warp = threadIdx.x >> 5, lane = threadIdx.x & 31;
    const int r0 = blockIdx.x * 32 + warp * 4;
    const float* u0 = g_u + (size_t)r0 * DINNER;
    float acc[4][5];
#pragma unroll
    for (int i = 0; i < 4; ++i)
#pragma unroll
        for (int j = 0; j < 5; ++j) acc[i][j] = 0.f;

    for (int k0 = 0; k0 < DINNER; k0 += 32) {
        float ua = u0[k0 + lane];
        float ub = u0[DINNER + k0 + lane];
        float uc = u0[2 * DINNER + k0 + lane];
        float ud = u0[3 * DINNER + k0 + lane];
#pragma unroll 4
        for (int j = 0; j < 32; ++j) {
            const float* wrow = g_wT + (size_t)(k0 + j) * NPROJP + lane;
            float w0 = wrow[0], w1 = wrow[32], w2 = wrow[64], w3 = wrow[96], w4 = wrow[128];
            float v0 = __shfl_sync(0xffffffffu, ua, j);
            float v1 = __shfl_sync(0xffffffffu, ub, j);
            float v2 = __shfl_sync(0xffffffffu, uc, j);
            float v3 = __shfl_sync(0xffffffffu, ud, j);
            acc[0][0] = fmaf(w0, v0, acc[0][0]); acc[0][1] = fmaf(w1, v0, acc[0][1]);
            acc[0][2] = fmaf(w2, v0, acc[0][2]); acc[0][3] = fmaf(w3, v0, acc[0][3]);
            acc[0][4] = fmaf(w4, v0, acc[0][4]);
            acc[1][0] = fmaf(w0, v1, acc[1][0]); acc[1][1] = fmaf(w1, v1, acc[1][1]);
            acc[1][2] = fmaf(w2, v1, acc[1][2]); acc[1][3] = fmaf(w3, v1, acc[1][3]);
            acc[1][4] = fmaf(w4, v1, acc[1][4]);
            acc[2][0] = fmaf(w0, v2, acc[2][0]); acc[2][1] = fmaf(w1, v2, acc[2][1]);
            acc[2][2] = fmaf(w2, v2, acc[2][2]); acc[2][3] = fmaf(w3, v2, acc[2][3]);
            acc[2][4] = fmaf(w4, v2, acc[2][4]);
            acc[3][0] = fmaf(w0, v3, acc[3][0]); acc[3][1] = fmaf(w1, v3, acc[3][1]);
            acc[3][2] = fmaf(w2, v3, acc[3][2]); acc[3][3] = fmaf(w3, v3, acc[3][3]);
            acc[3][4] = fmaf(w4, v3, acc[3][4]);
        }
    }
#pragma unroll
    for (int i = 0; i < 4; ++i) {
        const int r = r0 + i;
        const int b = r >> 12;       // r / SEQ
        const int l = r & (SEQ - 1);
#pragma unroll
        for (int jj = 0; jj < 5; ++jj) {
            int c = lane + 32 * jj;
            if (c < NPROJ) {
                float v = acc[i][jj] + bias[c];
                if (c < NH) {
                    float x = v + dt_bias[c];
                    float sp = (x > 20.f) ? x : log1pf(__expf(x));
                    g_dtT[((size_t)b * NH + c) * SEQ + l] = sp;
                } else if (c < NH + DSTATE) {
                    g_Bm[(size_t)r * DSTATE + (c - NH)] = v;
                } else {
                    g_Cm[(size_t)r * DSTATE + (c - NH - DSTATE)] = v;
                }
            }
        }
    }
}

// ---------------- selective scan: one warp per (b,d); 2 states / lane ----------------
__global__ __launch_bounds__(256) void scan_kernel(const float* __restrict__ A_log,
                                                   const float* __restrict__ Dp) {
    const int w = blockIdx.x * 8 + (threadIdx.x >> 5);
    const int lane = threadIdx.x & 31;
    const int b = w >> 11;       // w / 2048
    const int d = w & (DINNER - 1);
    const int h = d >> 7;        // headdim 128
    const int n0 = lane * 2;
    const float L2E = 1.4426950408889634f;
    const float a0 = -__expf(A_log[d * DSTATE + n0]) * L2E;
    const float a1 = -__expf(A_log[d * DSTATE + n0 + 1]) * L2E;
    const float Dd = Dp[d];
    float s0 = 0.f, s1 = 0.f;
    const float2* Bp = reinterpret_cast<const float2*>(g_Bm + (size_t)b * SEQ * DSTATE) + lane;
    const float2* Cp = reinterpret_cast<const float2*>(g_Cm + (size_t)b * SEQ * DSTATE) + lane;
    const float* up  = g_uT  + ((size_t)b * DINNER + d) * SEQ;
    const float* dtp = g_dtT + ((size_t)b * NH + h) * SEQ;
    float* yp = g_y1 + (size_t)b * SEQ * DINNER + d;

    for (int t0 = 0; t0 < SEQ; t0 += 32) {
        float ur = up[t0 + lane];
        float dr = dtp[t0 + lane];
#pragma unroll 8
        for (int j = 0; j < 32; ++j) {
            float ut = __shfl_sync(0xffffffffu, ur, j);
            float dt = __shfl_sync(0xffffffffu, dr, j);
            float2 Bv = *Bp; Bp += 32;
            float2 Cv = *Cp; Cp += 32;
            float e0 = ex2f(dt * a0);
            float e1 = ex2f(dt * a1);
            float du = dt * ut;
            s0 = fmaf(s0, e0, du * Bv.x);
            s1 = fmaf(s1, e1, du * Bv.y);
            float p = fmaf(s0, Cv.x, s1 * Cv.y);
            p += __shfl_xor_sync(0xffffffffu, p, 16);
            p += __shfl_xor_sync(0xffffffffu, p, 8);
            p += __shfl_xor_sync(0xffffffffu, p, 4);
            p += __shfl_xor_sync(0xffffffffu, p, 2);
            p += __shfl_xor_sync(0xffffffffu, p, 1);
            if (lane == 0) *yp = fmaf(ut, Dd, p);
            yp += DINNER;
        }
    }
}

// ---------------- gate with silu(z) + LayerNorm -> bf16 hi/lo (for out_proj) ----------------
__global__ __launch_bounds__(256) void ln_kernel(const float* __restrict__ nw,
                                                 const float* __restrict__ nb) {
    const int r = blockIdx.x;
    const float* yrow = g_y1 + (size_t)r * DINNER;
    const float* zrow = g_xz + (size_t)r * DXZ + DINNER;
    float v[8];
    float s = 0.f, q = 0.f;
#pragma unroll
    for (int j = 0; j < 8; ++j) {
        int i = threadIdx.x + j * 256;
        float z = zrow[i];
        float y = yrow[i] * (z / (1.f + __expf(-z)));
        v[j] = y;
        s += y;
        q = fmaf(y, y, q);
    }
    __shared__ float rs[8], rq[8];
    __shared__ float mv[2];
    const int wid = threadIdx.x >> 5, lane = threadIdx.x & 31;
#pragma unroll
    for (int o = 16; o; o >>= 1) {
        s += __shfl_xor_sync(0xffffffffu, s, o);
        q += __shfl_xor_sync(0xffffffffu, q, o);
    }
    if (lane == 0) { rs[wid] = s; rq[wid] = q; }
    __syncthreads();
    if (wid == 0) {
        float ts = (lane < 8) ? rs[lane] : 0.f;
        float tq = (lane < 8) ? rq[lane] : 0.f;
#pragma unroll
        for (int o = 4; o; o >>= 1) {
            ts += __shfl_xor_sync(0xffffffffu, ts, o);
            tq += __shfl_xor_sync(0xffffffffu, tq, o);
        }
        if (lane == 0) {
            float mean = ts * (1.f / DINNER);
            float var = tq * (1.f / DINNER) - mean * mean;
            mv[0] = mean;
            mv[1] = rsqrtf(var + 1e-5f);
        }
    }
    __syncthreads();
    const float mean = mv[0], rstd = mv[1];
#pragma unroll
    for (int j = 0; j < 8; ++j) {
        int i = threadIdx.x + j * 256;
        float o = fmaf((v[j] - mean) * rstd, nw[i], nb[i]);
        __nv_bfloat16 h = __float2bfloat16(o);
        size_t idx = (size_t)r * DINNER + i;
        g_Chi[idx] = h;
        g_Clo[idx] = __float2bfloat16(o - __bfloat162float(h));
    }
}

// ---------------- launch ----------------
extern "C" void kernel_launch(void* const* d_in, const int* in_sizes, int n_in,
                              void* d_out, int out_size) {
    (void)in_sizes; (void)n_in; (void)out_size;
    const float* hs   = (const float*)d_in[0];
    const float* inw  = (const float*)d_in[1];
    const float* cw   = (const float*)d_in[2];
    const float* cb   = (const float*)d_in[3];
    const float* dpw  = (const float*)d_in[4];
    const float* dpb  = (const float*)d_in[5];
    const float* dtb  = (const float*)d_in[6];
    const float* alog = (const float*)d_in[7];
    const float* Dv   = (const float*)d_in[8];
    const float* nw   = (const float*)d_in[9];
    const float* nb   = (const float*)d_in[10];
    const float* opw  = (const float*)d_in[11];
    float* out = (float*)d_out;

    __nv_bfloat16 *Ahi, *Alo, *Wihi, *Wilo, *Wohi, *Wolo, *Chi, *Clo;
    cudaGetSymbolAddress((void**)&Ahi,  g_Ahi);  cudaGetSymbolAddress((void**)&Alo,  g_Alo);
    cudaGetSymbolAddress((void**)&Wihi, g_Wihi); cudaGetSymbolAddress((void**)&Wilo, g_Wilo);
    cudaGetSymbolAddress((void**)&Wohi, g_Wohi); cudaGetSymbolAddress((void**)&Wolo, g_Wolo);
    cudaGetSymbolAddress((void**)&Chi,  g_Chi);  cudaGetSymbolAddress((void**)&Clo,  g_Clo);
    float* xz; cudaGetSymbolAddress((void**)&xz, g_xz);

    cudaFuncSetAttribute(mma_gemm, cudaFuncAttributeMaxDynamicSharedMemorySize, GEMM_SMEM);

    // split fp32 -> bf16 hi/lo
    split_kernel<<<(BL * DMODEL) / 1024, 256>>>(hs, Ahi, Alo);
    split_kernel<<<(DXZ * DMODEL) / 1024, 256>>>(inw, Wihi, Wilo);
    split_kernel<<<(DMODEL * DINNER) / 1024, 256>>>(opw, Wohi, Wolo);
    // dt_proj_w transpose (padded)
    wT_kernel<<<(DINNER * NPROJP + 255) / 256, 256>>>(dpw);
    // in_proj GEMM (mma.sync bf16 split-3): (8192 x 4096) = A(8192x1024) @ W(4096x1024)^T
    mma_gemm<<<dim3(DXZ / 128, BL / 128), 512, GEMM_SMEM>>>(Ahi, Alo, Wihi, Wilo, xz, DXZ, DMODEL);
    // conv + silu (+ transpose into uT)
    conv_silu_kernel<<<dim3(DINNER / 32, SEQ / 32, NBATCH), dim3(32, 32)>>>(cw, cb);
    // x_proj skinny GEMM + softplus(dt) + split B/C
    xproj_kernel<<<BL / 32, 256>>>(dpb, dtb);
    // selective scan
    scan_kernel<<<(NBATCH * DINNER) / 8, 256>>>(alog, Dv);
    // gate + layernorm -> bf16 split
    ln_kernel<<<BL, 256>>>(nw, nb);
    // out_proj GEMM: (8192 x 1024) = C(8192x2048) @ W(1024x2048)^T
    mma_gemm<<<dim3(DMODEL / 128, BL / 128), 512, GEMM_SMEM>>>(Chi, Clo, Wohi, Wolo, out, DMODEL, DINNER);
}

// round 14
// speedup vs baseline: 1.2673x; 1.2673x over previous
#include <cuda_runtime.h>
#include <cuda_fp16.h>
#include <cuda_bf16.h>
#include <cstdint>

#define SEQ    4096
#define DMODEL 1024
#define DINNER 2048
#define DSTATE 64
#define NH     16
#define NBATCH 2
#define BL     (NBATCH * SEQ)      /* 8192 rows */
#define DXZ    (2 * DINNER)        /* 4096 */
#define NPROJ  (NH + 2 * DSTATE)   /* 144 */
#define NPROJP 160                 /* padded */

// ---------------- scratch (device globals: no allocation allowed) ----------------
__device__ float g_xz [BL * DXZ];              // in_proj output (x | z)
__device__ float g_u  [BL * DINNER];           // conv+silu (b,l,d)
__device__ float g_uT [NBATCH * DINNER * SEQ]; // (b,d,l)
__device__ float g_dtT[NBATCH * NH * SEQ];     // softplus(dt), (b,h,l)
__device__ float g_Bm [BL * DSTATE];           // (b,l,n)
__device__ float g_Cm [BL * DSTATE];
__device__ float g_y1 [BL * DINNER];           // scan out + u*D
__device__ float g_wT [DINNER * NPROJP];       // dt_proj_w transposed, padded

// fp16 operands for tensor-core GEMMs (activations split-2, weights single)
__device__ __align__(16) __half g_Ah[BL * DMODEL],  g_Al[BL * DMODEL];   // hidden_states hi/lo
__device__ __align__(16) __half g_Wi[DXZ * DMODEL];                      // in_proj_w fp16
__device__ __align__(16) __half g_Wo[DMODEL * DINNER];                   // out_proj_w fp16
__device__ __align__(16) __half g_Ch[BL * DINNER],  g_Cl[BL * DINNER];   // LN output hi/lo

__device__ __forceinline__ float ex2f(float x) {
    float r;
    asm("ex2.approx.ftz.f32 %0, %1;" : "=f"(r) : "f"(x));
    return r;
}
__device__ __forceinline__ uint32_t smem_u32(const void* p) {
    uint32_t a;
    asm("{ .reg .u64 t; cvta.to.shared.u64 t, %1; cvt.u32.u64 %0, t; }" : "=r"(a) : "l"(p));
    return a;
}

// ============ split fp32 -> fp16 hi/lo ============
__global__ __launch_bounds__(256) void split2_kernel(const float* __restrict__ x,
                                                     __half* __restrict__ hi,
                                                     __half* __restrict__ lo) {
    int i = (blockIdx.x * 256 + threadIdx.x) * 4;
    float4 v = *(const float4*)(x + i);
    float f[4] = {v.x, v.y, v.z, v.w};
#pragma unroll
    for (int j = 0; j < 4; ++j) {
        __half h = __float2half(f[j]);
        hi[i + j] = h;
        lo[i + j] = __float2half(f[j] - __half2float(h));
    }
}

// ============ cast fp32 -> fp16 ============
__global__ __launch_bounds__(256) void cast_kernel(const float* __restrict__ x,
                                                   __half* __restrict__ o) {
    int i = (blockIdx.x * 256 + threadIdx.x) * 4;
    float4 v = *(const float4*)(x + i);
    o[i + 0] = __float2half(v.x);
    o[i + 1] = __float2half(v.y);
    o[i + 2] = __float2half(v.z);
    o[i + 3] = __float2half(v.w);
}

// ============ mma.sync fp16 GEMM: C[M,N] = Ahi@B^T + Alo@B^T (2 K-sections) ============
// 128x128 tile, BK=64, 256 threads (8 warps, 64x32 per warp), 2-stage cp.async
// pipeline, XOR-swizzled smem. smem: As[2] @0, Bs[2] @32768.
#define STG_BYTES 16384
#define GEMM_SMEM 65536

__device__ __forceinline__ void stage_load(const __half* __restrict__ A,
                                           const __half* __restrict__ B,
                                           int K, int bm, int bn, int k0,
                                           char* smA, char* smB, int tid) {
#pragma unroll
    for (int i = 0; i < 4; ++i) {
        int q = tid + i * 256;          // 0..1023 chunk id
        int row = q >> 3, c = q & 7;    // 128 rows x 8 chunks(16B) per row
        int pc = c ^ (row & 7);         // swizzle
        uint32_t da = smem_u32(smA + (row * 8 + pc) * 16);
        const void* ga = (const void*)(A + (size_t)(bm + row) * K + k0 + c * 8);
        asm volatile("cp.async.cg.shared.global [%0], [%1], 16;" :: "r"(da), "l"(ga));
        uint32_t db = smem_u32(smB + (row * 8 + pc) * 16);
        const void* gb = (const void*)(B + (size_t)(bn + row) * K + k0 + c * 8);
        asm volatile("cp.async.cg.shared.global [%0], [%1], 16;" :: "r"(db), "l"(gb));
    }
}

__global__ __launch_bounds__(256) void mma_gemm(const __half* __restrict__ Ahi,
                                                const __half* __restrict__ Alo,
                                                const __half* __restrict__ B,
                                                float* __restrict__ C, int N, int K) {
    extern __shared__ char smem[];
    const int tid = threadIdx.x;
    const int wid = tid >> 5, lane = tid & 31;
    const int wm = (wid >> 2) * 64;     // warp m offset in tile
    const int wn = (wid & 3) * 32;      // warp n offset in tile
    const int bm = blockIdx.y * 128;
    const int bn = blockIdx.x * 128;

    float acc[4][4][4];
#pragma unroll
    for (int a = 0; a < 4; ++a)
#pragma unroll
        for (int b = 0; b < 4; ++b)
#pragma unroll
            for (int c = 0; c < 4; ++c) acc[a][b][c] = 0.f;

    const int ksec = K >> 6;          // chunks per section
    const int nch = 2 * ksec;         // 2 sections: Ahi, Alo

    // prologue: stage 0 = chunk 0 (Ahi, k0 = 0)
    stage_load(Ahi, B, K, bm, bn, 0, smem, smem + 2 * STG_BYTES, tid);
    asm volatile("cp.async.commit_group;" ::: "memory");

    for (int cc = 0; cc < nch; ++cc) {
        const int st = cc & 1;
        if (cc + 1 < nch) {
            const int c1 = cc + 1;
            const __half* As = (c1 < ksec) ? Ahi : Alo;
            const int k1 = ((c1 < ksec) ? c1 : (c1 - ksec)) << 6;
            const int st1 = c1 & 1;
            stage_load(As, B, K, bm, bn, k1,
                       smem + st1 * STG_BYTES, smem + 2 * STG_BYTES + st1 * STG_BYTES, tid);
            asm volatile("cp.async.commit_group;" ::: "memory");
            asm volatile("cp.async.wait_group 1;" ::: "memory");
        } else {
            asm volatile("cp.async.wait_group 0;" ::: "memory");
        }
        __syncthreads();

        const char* sA = smem + st * STG_BYTES;
        const char* sB = smem + 2 * STG_BYTES + st * STG_BYTES;
#pragma unroll
        for (int kk = 0; kk < 4; ++kk) {        // 4 x k16 within BK=64
            uint32_t a[4][4];
#pragma unroll
            for (int mt = 0; mt < 4; ++mt) {
                int row = wm + mt * 16 + (lane & 15);
                int c = kk * 2 + (lane >> 4);
                uint32_t ad = smem_u32(sA + (row * 8 + (c ^ (row & 7))) * 16);
                asm volatile("ldmatrix.sync.aligned.m8n8.x4.shared.b16 {%0,%1,%2,%3}, [%4];"
                             : "=r"(a[mt][0]), "=r"(a[mt][1]), "=r"(a[mt][2]), "=r"(a[mt][3])
                             : "r"(ad));
            }
            uint32_t b[4][2];
#pragma unroll
            for (int pt = 0; pt < 2; ++pt) {
                int row = wn + pt * 16 + (lane & 15);
                int c = kk * 2 + (lane >> 4);
                uint32_t bd = smem_u32(sB + (row * 8 + (c ^ (row & 7))) * 16);
                uint32_t r0, r1, r2, r3;
                asm volatile("ldmatrix.sync.aligned.m8n8.x4.shared.b16 {%0,%1,%2,%3}, [%4];"
                             : "=r"(r0), "=r"(r1), "=r"(r2), "=r"(r3) : "r"(bd));
                b[2 * pt][0] = r0; b[2 * pt + 1][0] = r1;
                b[2 * pt][1] = r2; b[2 * pt + 1][1] = r3;
            }
#pragma unroll
            for (int mt = 0; mt < 4; ++mt)
#pragma unroll
                for (int nt = 0; nt < 4; ++nt) {
                    asm volatile(
                        "mma.sync.aligned.m16n8k16.row.col.f32.f16.f16.f32 "
                        "{%0,%1,%2,%3}, {%4,%5,%6,%7}, {%8,%9}, {%0,%1,%2,%3};"
                        : "+f"(acc[mt][nt][0]), "+f"(acc[mt][nt][1]),
                          "+f"(acc[mt][nt][2]), "+f"(acc[mt][nt][3])
                        : "r"(a[mt][0]), "r"(a[mt][1]), "r"(a[mt][2]), "r"(a[mt][3]),
                          "r"(b[nt][0]), "r"(b[nt][1]));
                }
        }
        __syncthreads();
    }

    // epilogue
    const int g = lane >> 2, t = lane & 3;
#pragma unroll
    for (int mt = 0; mt < 4; ++mt) {
        int row0 = bm + wm + mt * 16 + g;
#pragma unroll
        for (int nt = 0; nt < 4; ++nt) {
            int col = bn + wn + nt * 8 + 2 * t;
            *(float2*)(C + (size_t)row0 * N + col) = make_float2(acc[mt][nt][0], acc[mt][nt][1]);
            *(float2*)(C + (size_t)(row0 + 8) * N + col) = make_float2(acc[mt][nt][2], acc[mt][nt][3]);
        }
    }
}

// ---------------- transpose dt_proj_w -> wT[k][c] (padded to 160) ----------------
__global__ void wT_kernel(const float* __restrict__ w) {
    int idx = blockIdx.x * 256 + threadIdx.x;
    if (idx >= DINNER * NPROJP) return;
    int k = idx / NPROJP, c = idx % NPROJP;
    g_wT[idx] = (c < NPROJ) ? w[(size_t)c * DINNER + k] : 0.f;
}

// ---------------- depthwise causal conv (w=4) + silu, writes u and uT ----------------
__global__ __launch_bounds__(1024) void conv_silu_kernel(const float* __restrict__ cw,
                                                         const float* __restrict__ cb) {
    __shared__ float sm[32][33];
    const int tx = threadIdx.x, ty = threadIdx.y;
    const int b = blockIdx.z;
    const int d = blockIdx.x * 32 + tx;
    const int l = blockIdx.y * 32 + ty;
    const float* xcol = g_xz + (size_t)b * SEQ * DXZ + d;  // x = cols [0,2048)
    float acc = cb[d];
#pragma unroll
    for (int k = 0; k < 4; ++k) {
        int ll = l - 3 + k;
        if (ll >= 0) acc = fmaf(xcol[(size_t)ll * DXZ], cw[d * 4 + k], acc);
    }
    float u = acc / (1.f + __expf(-acc));  // silu
    g_u[((size_t)b * SEQ + l) * DINNER + d] = u;
    sm[ty][tx] = u;
    __syncthreads();
    const int dd = blockIdx.x * 32 + ty;
    const int ll2 = blockIdx.y * 32 + tx;
    g_uT[((size_t)b * DINNER + dd) * SEQ + ll2] = sm[tx][ty];
}

// ---------------- x_proj: warp per 4 rows; lane owns cols lane+32j ----------------
__global__ __launch_bounds__(256) void xproj_kernel(const float* __restrict__ bias,
                                                    const float* __restrict__ dt_bias) {
    const int warp = threadIdx.x >> 5, lane = threadIdx.x & 31;
    const int r0 = blockIdx.x * 32 + warp * 4;
    const float* u0 = g_u + (size_t)r0 * DINNER;
    float acc[4][5];
#pragma unroll
    for (int i = 0; i < 4; ++i)
#pragma unroll
        for (int j = 0; j < 5; ++j) acc[i][j] = 0.f;

    for (int k0 = 0; k0 < DINNER; k0 += 32) {
        float ua = u0[k0 + lane];
        float ub = u0[DINNER + k0 + lane];
        float uc = u0[2 * DINNER + k0 + lane];
        float ud = u0[3 * DINNER + k0 + lane];
#pragma unroll 4
        for (int j = 0; j < 32; ++j) {
            const float* wrow = g_wT + (size_t)(k0 + j) * NPROJP + lane;
            float w0 = wrow[0], w1 = wrow[32], w2 = wrow[64], w3 = wrow[96], w4 = wrow[128];
            float v0 = __shfl_sync(0xffffffffu, ua, j);
            float v1 = __shfl_sync(0xffffffffu, ub, j);
            float v2 = __shfl_sync(0xffffffffu, uc, j);
            float v3 = __shfl_sync(0xffffffffu, ud, j);
            acc[0][0] = fmaf(w0, v0, acc[0][0]); acc[0][1] = fmaf(w1, v0, acc[0][1]);
            acc[0][2] = fmaf(w2, v0, acc[0][2]); acc[0][3] = fmaf(w3, v0, acc[0][3]);
            acc[0][4] = fmaf(w4, v0, acc[0][4]);
            acc[1][0] = fmaf(w0, v1, acc[1][0]); acc[1][1] = fmaf(w1, v1, acc[1][1]);
            acc[1][2] = fmaf(w2, v1, acc[1][2]); acc[1][3] = fmaf(w3, v1, acc[1][3]);
            acc[1][4] = fmaf(w4, v1, acc[1][4]);
            acc[2][0] = fmaf(w0, v2, acc[2][0]); acc[2][1] = fmaf(w1, v2, acc[2][1]);
            acc[2][2] = fmaf(w2, v2, acc[2][2]); acc[2][3] = fmaf(w3, v2, acc[2][3]);
            acc[2][4] = fmaf(w4, v2, acc[2][4]);
            acc[3][0] = fmaf(w0, v3, acc[3][0]); acc[3][1] = fmaf(w1, v3, acc[3][1]);
            acc[3][2] = fmaf(w2, v3, acc[3][2]); acc[3][3] = fmaf(w3, v3, acc[3][3]);
            acc[3][4] = fmaf(w4, v3, acc[3][4]);
        }
    }
#pragma unroll
    for (int i = 0; i < 4; ++i) {
        const int r = r0 + i;
        const int b = r >> 12;       // r / SEQ
        const int l = r & (SEQ - 1);
#pragma unroll
        for (int jj = 0; jj < 5; ++jj) {
            int c = lane + 32 * jj;
            if (c < NPROJ) {
                float v = acc[i][jj] + bias[c];
                if (c < NH) {
                    float x = v + dt_bias[c];
                    float sp = (x > 20.f) ? x : log1pf(__expf(x));
                    g_dtT[((size_t)b * NH + c) * SEQ + l] = sp;
                } else if (c < NH + DSTATE) {
                    g_Bm[(size_t)r * DSTATE + (c - NH)] = v;
                } else {
                    g_Cm[(size_t)r * DSTATE + (c - NH - DSTATE)] = v;
                }
            }
        }
    }
}

// ---------------- selective scan: one warp per (b,d); 2 states / lane ----------------
__global__ __launch_bounds__(256) void scan_kernel(const float* __restrict__ A_log,
                                                   const float* __restrict__ Dp) {
    const int w = blockIdx.x * 8 + (threadIdx.x >> 5);
    const int lane = threadIdx.x & 31;
    const int b = w >> 11;       // w / 2048
    const int d = w & (DINNER - 1);
    const int h = d >> 7;        // headdim 128
    const int n0 = lane * 2;
    const float L2E = 1.4426950408889634f;
    const float a0 = -__expf(A_log[d * DSTATE + n0]) * L2E;
    const float a1 = -__expf(A_log[d * DSTATE + n0 + 1]) * L2E;
    const float Dd = Dp[d];
    float s0 = 0.f, s1 = 0.f;
    const float2* Bp = reinterpret_cast<const float2*>(g_Bm + (size_t)b * SEQ * DSTATE) + lane;
    const float2* Cp = reinterpret_cast<const float2*>(g_Cm + (size_t)b * SEQ * DSTATE) + lane;
    const float* up  = g_uT  + ((size_t)b * DINNER + d) * SEQ;
    const float* dtp = g_dtT + ((size_t)b * NH + h) * SEQ;
    float* yp = g_y1 + (size_t)b * SEQ * DINNER + d;

    for (int t0 = 0; t0 < SEQ; t0 += 32) {
        float ur = up[t0 + lane];
        float dr = dtp[t0 + lane];
#pragma unroll 8
        for (int j = 0; j < 32; ++j) {
            float ut = __shfl_sync(0xffffffffu, ur, j);
            float dt = __shfl_sync(0xffffffffu, dr, j);
            float2 Bv = *Bp; Bp += 32;
            float2 Cv = *Cp; Cp += 32;
            float e0 = ex2f(dt * a0);
            float e1 = ex2f(dt * a1);
            float du = dt * ut;
            s0 = fmaf(s0, e0, du * Bv.x);
            s1 = fmaf(s1, e1, du * Bv.y);
            float p = fmaf(s0, Cv.x, s1 * Cv.y);
            p += __shfl_xor_sync(0xffffffffu, p, 16);
            p += __shfl_xor_sync(0xffffffffu, p, 8);
            p += __shfl_xor_sync(0xffffffffu, p, 4);
            p += __shfl_xor_sync(0xffffffffu, p, 2);
            p += __shfl_xor_sync(0xffffffffu, p, 1);
            if (lane == 0) *yp = fmaf(ut, Dd, p);
            yp += DINNER;
        }
    }
}

// ---------------- gate with silu(z) + LayerNorm -> fp16 hi/lo (for out_proj) ----------------
__global__ __launch_bounds__(256) void ln_kernel(const float* __restrict__ nw,
                                                 const float* __restrict__ nb) {
    const int r = blockIdx.x;
    const float* yrow = g_y1 + (size_t)r * DINNER;
    const float* zrow = g_xz + (size_t)r * DXZ + DINNER;
    float v[8];
    float s = 0.f, q = 0.f;
#pragma unroll
    for (int j = 0; j < 8; ++j) {
        int i = threadIdx.x + j * 256;
        float z = zrow[i];
        float y = yrow[i] * (z / (1.f + __expf(-z)));
        v[j] = y;
        s += y;
        q = fmaf(y, y, q);
    }
    __shared__ float rs[8], rq[8];
    __shared__ float mv[2];
    const int wid = threadIdx.x >> 5, lane = threadIdx.x & 31;
#pragma unroll
    for (int o = 16; o; o >>= 1) {
        s += __shfl_xor_sync(0xffffffffu, s, o);
        q += __shfl_xor_sync(0xffffffffu, q, o);
    }
    if (lane == 0) { rs[wid] = s; rq[wid] = q; }
    __syncthreads();
    if (wid == 0) {
        float ts = (lane < 8) ? rs[lane] : 0.f;
        float tq = (lane < 8) ? rq[lane] : 0.f;
#pragma unroll
        for (int o = 4; o; o >>= 1) {
            ts += __shfl_xor_sync(0xffffffffu, ts, o);
            tq += __shfl_xor_sync(0xffffffffu, tq, o);
        }
        if (lane == 0) {
            float mean = ts * (1.f / DINNER);
            float var = tq * (1.f / DINNER) - mean * mean;
            mv[0] = mean;
            mv[1] = rsqrtf(var + 1e-5f);
        }
    }
    __syncthreads();
    const float mean = mv[0], rstd = mv[1];
#pragma unroll
    for (int j = 0; j < 8; ++j) {
        int i = threadIdx.x + j * 256;
        float o = fmaf((v[j] - mean) * rstd, nw[i], nb[i]);
        __half h = __float2half(o);
        size_t idx = (size_t)r * DINNER + i;
        g_Ch[idx] = h;
        g_Cl[idx] = __float2half(o - __half2float(h));
    }
}

// ---------------- launch ----------------
extern "C" void kernel_launch(void* const* d_in, const int* in_sizes, int n_in,
                              void* d_out, int out_size) {
    (void)in_sizes; (void)n_in; (void)out_size;
    const float* hs   = (const float*)d_in[0];
    const float* inw  = (const float*)d_in[1];
    const float* cw   = (const float*)d_in[2];
    const float* cb   = (const float*)d_in[3];
    const float* dpw  = (const float*)d_in[4];
    const float* dpb  = (const float*)d_in[5];
    const float* dtb  = (const float*)d_in[6];
    const float* alog = (const float*)d_in[7];
    const float* Dv   = (const float*)d_in[8];
    const float* nw   = (const float*)d_in[9];
    const float* nb   = (const float*)d_in[10];
    const float* opw  = (const float*)d_in[11];
    float* out = (float*)d_out;

    __half *Ah, *Al, *Wi, *Wo, *Ch, *Cl;
    cudaGetSymbolAddress((void**)&Ah, g_Ah); cudaGetSymbolAddress((void**)&Al, g_Al);
    cudaGetSymbolAddress((void**)&Wi, g_Wi); cudaGetSymbolAddress((void**)&Wo, g_Wo);
    cudaGetSymbolAddress((void**)&Ch, g_Ch); cudaGetSymbolAddress((void**)&Cl, g_Cl);
    float* xz; cudaGetSymbolAddress((void**)&xz, g_xz);

    cudaFuncSetAttribute(mma_gemm, cudaFuncAttributeMaxDynamicSharedMemorySize, GEMM_SMEM);

    // prepare fp16 operands
    split2_kernel<<<(BL * DMODEL) / 1024, 256>>>(hs, Ah, Al);
    cast_kernel<<<(DXZ * DMODEL) / 1024, 256>>>(inw, Wi);
    cast_kernel<<<(DMODEL * DINNER) / 1024, 256>>>(opw, Wo);
    // dt_proj_w transpose (padded)
    wT_kernel<<<(DINNER * NPROJP + 255) / 256, 256>>>(dpw);
    // in_proj GEMM (mma.sync fp16, 2 K-sections): (8192 x 4096) = A(8192x1024) @ W(4096x1024)^T
    mma_gemm<<<dim3(DXZ / 128, BL / 128), 256, GEMM_SMEM>>>(Ah, Al, Wi, xz, DXZ, DMODEL);
    // conv + silu (+ transpose into uT)
    conv_silu_kernel<<<dim3(DINNER / 32, SEQ / 32, NBATCH), dim3(32, 32)>>>(cw, cb);
    // x_proj skinny GEMM + softplus(dt) + split B/C
    xproj_kernel<<<BL / 32, 256>>>(dpb, dtb);
    // selective scan
    scan_kernel<<<(NBATCH * DINNER) / 8, 256>>>(alog, Dv);
    // gate + layernorm -> fp16 hi/lo
    ln_kernel<<<BL, 256>>>(nw, nb);
    // out_proj GEMM: (8192 x 1024) = C(8192x2048) @ W(1024x2048)^T
    mma_gemm<<<dim3(DMODEL / 128, BL / 128), 256, GEMM_SMEM>>>(Ch, Cl, Wo, out, DMODEL, DINNER);
}